// round 12
// baseline (speedup 1.0000x reference)
#include <cuda_runtime.h>
#include <cuda_bf16.h>
#include <cstdint>

#define TT 2048
#define CC 64
#define NCH 32
#define NT 256

// ---- smem byte offsets ----
// K  tiles [64s x 128m] stride 272B   (hi, lo)
// MT tiles [32n x 128m] stride 272B
// VT tiles [32n x  64s] stride 144B
// A  tiles [64t x  64s] stride 144B
// m0f fp32 [128m x 32n]
#define S_KH 0
#define S_KL 17408
#define S_MH 34816
#define S_ML 43520
#define S_VH 52224
#define S_VL 56832
#define S_AH 61440
#define S_AL 70656
#define S_M0 79872
#define S_G  96256
#define S_WS 96512
#define S_WG 96768
#define S_EG 97024
#define S_SC 97280
#define SMEMB 97536

static __device__ __forceinline__ uint32_t su32(const void* p) {
    uint32_t a;
    asm("{ .reg .u64 t; cvta.to.shared.u64 t, %1; cvt.u32.u64 %0, t; }" : "=r"(a) : "l"(p));
    return a;
}
static __device__ __forceinline__ void ldmA(uint32_t a[4], uint32_t addr) {
    asm volatile("ldmatrix.sync.aligned.m8n8.x4.shared.b16 {%0,%1,%2,%3}, [%4];"
        : "=r"(a[0]), "=r"(a[1]), "=r"(a[2]), "=r"(a[3]) : "r"(addr));
}
static __device__ __forceinline__ void ldmB4(uint32_t b[4], uint32_t addr) {
    asm volatile("ldmatrix.sync.aligned.m8n8.x4.shared.b16 {%0,%1,%2,%3}, [%4];"
        : "=r"(b[0]), "=r"(b[1]), "=r"(b[2]), "=r"(b[3]) : "r"(addr));
}
static __device__ __forceinline__ void ldmT(uint32_t a[4], uint32_t addr) {
    asm volatile("ldmatrix.sync.aligned.m8n8.x4.trans.shared.b16 {%0,%1,%2,%3}, [%4];"
        : "=r"(a[0]), "=r"(a[1]), "=r"(a[2]), "=r"(a[3]) : "r"(addr));
}
static __device__ __forceinline__ void mma16(float c[4], const uint32_t a[4], uint32_t b0, uint32_t b1) {
    asm volatile("mma.sync.aligned.m16n8k16.row.col.f32.bf16.bf16.f32 "
        "{%0,%1,%2,%3}, {%4,%5,%6,%7}, {%8,%9}, {%0,%1,%2,%3};"
        : "+f"(c[0]), "+f"(c[1]), "+f"(c[2]), "+f"(c[3])
        : "r"(a[0]), "r"(a[1]), "r"(a[2]), "r"(a[3]), "r"(b0), "r"(b1));
}
static __device__ __forceinline__ void spl(float x, __nv_bfloat16& h, __nv_bfloat16& l) {
    h = __float2bfloat16_rn(x);
    l = __float2bfloat16_rn(x - __bfloat162float(h));
}
static __device__ __forceinline__ void sp2(float x0, float x1, uint32_t& hi, uint32_t& lo) {
    __nv_bfloat16 h0, l0, h1, l1;
    spl(x0, h0, l0); spl(x1, h1, l1);
    hi = (uint32_t)__bfloat16_as_ushort(h0) | ((uint32_t)__bfloat16_as_ushort(h1) << 16);
    lo = (uint32_t)__bfloat16_as_ushort(l0) | ((uint32_t)__bfloat16_as_ushort(l1) << 16);
}
// exp2(x) for x <= 0, FFMA-only
static __device__ __forceinline__ float ex2n(float x) {
    float xc = fmaxf(x, -150.f);
    float xf = floorf(xc);
    float f  = xc - xf;
    float p = 1.54035e-4f;
    p = fmaf(p, f, 1.3335581e-3f);
    p = fmaf(p, f, 9.6181291e-3f);
    p = fmaf(p, f, 5.5504109e-2f);
    p = fmaf(p, f, 2.4022651e-1f);
    p = fmaf(p, f, 6.9314718e-1f);
    p = fmaf(p, f, 1.0f);
    float r = __int_as_float(__float_as_int(p) + (((int)xf) << 23));
    return (xc <= -126.f) ? 0.f : r;
}

__global__ void __launch_bounds__(NT, 2)
lmm_hmma(const float* __restrict__ q, const float* __restrict__ kk,
         const float* __restrict__ v, const float* __restrict__ alpha,
         const float* __restrict__ rho, const float* __restrict__ lam,
         const float* __restrict__ init, float* __restrict__ out)
{
    extern __shared__ char sm[];
    const uint32_t sb = su32(sm);
    const int tid = threadIdx.x, warp = tid >> 5, lane = tid & 31;
    const int gid = lane >> 2, tig = lane & 3;
    const int b = blockIdx.x >> 2, vq = blockIdx.x & 3;
    const int rt = warp & 3;      // row tile (t) for S/QM0/AV
    const int ch = warp >> 2;     // col half: S cols ch*32; QM0/AV cols ch*16
    float* Gs  = (float*)(sm + S_G);
    float* WSs = (float*)(sm + S_WS);
    float* WGs = (float*)(sm + S_WG);
    float* EGs = (float*)(sm + S_EG);
    float* m0f = (float*)(sm + S_M0);

    const uint32_t laneA144 = (uint32_t)(lane & 15) * 144u + (uint32_t)((lane >> 4) << 4);
    const uint32_t laneB272x4 = (uint32_t)(lane & 7) * 272u + (uint32_t)(((lane >> 3) & 1) << 4)
                              + (uint32_t)(lane >> 4) * (8u * 272u);
    const uint32_t laneB144x4 = (uint32_t)(lane & 7) * 144u + (uint32_t)(((lane >> 3) & 1) << 4)
                              + (uint32_t)(lane >> 4) * (8u * 144u);
    // trans A-frag lane offset (K^T from K [s x m] tiles, 272B rows)
    const uint32_t laneT = ((uint32_t)(lane & 7) + (uint32_t)((lane >> 4) << 3)) * 272u
                         + (uint32_t)(lane & 8) * 2u;

    // ---- init m0f fp32 [128m x 32n] ----
    for (int i = tid; i < 1024; i += NT) {
        int m = i >> 3, n4 = (i & 7) << 2;
        *(float4*)(m0f + m * 32 + n4) =
            *(const float4*)(init + (size_t)b * 16384 + (size_t)m * 128 + vq * 32 + n4);
    }
    __syncthreads();

    for (int c = 0; c < NCH; c++) {
        const size_t tb0 = (size_t)b * TT + (size_t)c * CC;

        // ---- V prefetch [64s x 32n] -> 8 regs ----
        float vreg[8];
        #pragma unroll
        for (int ii = 0; ii < 8; ii++) {
            int i = tid + ii * NT;
            vreg[ii] = v[(tb0 + (size_t)(i >> 5)) * 128 + vq * 32 + (i & 31)];
        }
        // ---- scalars (warp 0) ----
        if (warp == 0) {
            float x = log2f(fmaxf(lam[tb0 + lane], 1e-37f));
            #pragma unroll
            for (int o = 1; o < 32; o <<= 1) { float y = __shfl_up_sync(~0u, x, o); if (lane >= o) x += y; }
            float tot = __shfl_sync(~0u, x, 31);
            float y2 = log2f(fmaxf(lam[tb0 + 32 + lane], 1e-37f));
            #pragma unroll
            for (int o = 1; o < 32; o <<= 1) { float y = __shfl_up_sync(~0u, y2, o); if (lane >= o) y2 += y; }
            float g2 = tot + y2;
            float g63 = __shfl_sync(~0u, g2, 31);
            float w0 = rho[tb0 + lane] * alpha[tb0 + lane];
            float w1 = rho[tb0 + 32 + lane] * alpha[tb0 + 32 + lane];
            Gs[lane] = x;            Gs[32 + lane] = g2;
            WSs[lane] = w0;          WSs[32 + lane] = w1;
            EGs[lane] = ex2n(x);     EGs[32 + lane] = ex2n(g2);
            WGs[lane] = ex2n(g63 - x) * w0;
            WGs[32 + lane] = ex2n(g63 - g2) * w1;
            if (lane == 31) *(float*)(sm + S_SC) = ex2n(g63);
        }
        // ---- K split tiles [64s x 128m] ----
        for (int i = tid; i < 2048; i += NT) {
            int t = i >> 5, c4 = (i & 31) << 2;
            uint32_t o = (uint32_t)t * 272u + (uint32_t)(c4 << 1);
            float4 f = *(const float4*)(kk + (tb0 + t) * 128 + c4);
            uint32_t h0, l0, h1, l1;
            sp2(f.x, f.y, h0, l0); sp2(f.z, f.w, h1, l1);
            *(uint32_t*)(sm + S_KH + o) = h0; *(uint32_t*)(sm + S_KH + o + 4) = h1;
            *(uint32_t*)(sm + S_KL + o) = l0; *(uint32_t*)(sm + S_KL + o + 4) = l1;
        }
        // ---- M^T split tiles [32n x 128m] from m0f ----
        for (int i = tid; i < 4096; i += NT) {
            int m = i >> 5, n = i & 31;
            __nv_bfloat16 h, l; spl(m0f[m * 32 + n], h, l);
            uint32_t o = (uint32_t)n * 272u + (uint32_t)(m << 1);
            *(__nv_bfloat16*)(sm + S_MH + o) = h;
            *(__nv_bfloat16*)(sm + S_ML + o) = l;
        }
        __syncthreads();   // sync1

        // ---- GEMM1: S = Q K^T (skip ct-half above diag) and QM0 (K=128) ----
        const bool sact = (rt >= 2 * ch);   // S tile (rt, ch) lives in lower triangle
        float sS[4][4], sQ[2][4];
        #pragma unroll
        for (int j = 0; j < 4; j++)
            #pragma unroll
            for (int e = 0; e < 4; e++) sS[j][e] = 0.f;
        #pragma unroll
        for (int j = 0; j < 2; j++)
            #pragma unroll
            for (int e = 0; e < 4; e++) sQ[j][e] = 0.f;
        {
            const float* qr0 = q + (tb0 + (size_t)(rt * 16 + gid)) * 128 + 2 * tig;
            #pragma unroll
            for (int ks = 0; ks < 8; ks++) {
                // Q fragments straight from gmem (layout = ldmA output layout)
                uint32_t qa[4], ql[4];
                {
                    float2 f0 = *(const float2*)(qr0 + ks * 16);
                    float2 f1 = *(const float2*)(qr0 + 8 * 128 + ks * 16);
                    float2 f2 = *(const float2*)(qr0 + ks * 16 + 8);
                    float2 f3 = *(const float2*)(qr0 + 8 * 128 + ks * 16 + 8);
                    sp2(f0.x, f0.y, qa[0], ql[0]);
                    sp2(f1.x, f1.y, qa[1], ql[1]);
                    sp2(f2.x, f2.y, qa[2], ql[2]);
                    sp2(f3.x, f3.y, qa[3], ql[3]);
                }
                if (sact) {
                    uint32_t bh[4], bl[4];
                    uint32_t kB = sb + S_KH + (uint32_t)(ch * 32) * 272u + ks * 32 + laneB272x4;
                    ldmB4(bh, kB); ldmB4(bl, kB + (S_KL - S_KH));
                    mma16(sS[0], qa, bh[0], bh[1]); mma16(sS[0], qa, bl[0], bl[1]); mma16(sS[0], ql, bh[0], bh[1]);
                    mma16(sS[1], qa, bh[2], bh[3]); mma16(sS[1], qa, bl[2], bl[3]); mma16(sS[1], ql, bh[2], bh[3]);
                    kB = sb + S_KH + (uint32_t)(ch * 32 + 16) * 272u + ks * 32 + laneB272x4;
                    ldmB4(bh, kB); ldmB4(bl, kB + (S_KL - S_KH));
                    mma16(sS[2], qa, bh[0], bh[1]); mma16(sS[2], qa, bl[0], bl[1]); mma16(sS[2], ql, bh[0], bh[1]);
                    mma16(sS[3], qa, bh[2], bh[3]); mma16(sS[3], qa, bl[2], bl[3]); mma16(sS[3], ql, bh[2], bh[3]);
                }
                {
                    uint32_t bh[4], bl[4];
                    uint32_t mB = sb + S_MH + (uint32_t)(ch * 16) * 272u + ks * 32 + laneB272x4;
                    ldmB4(bh, mB); ldmB4(bl, mB + (S_ML - S_MH));
                    mma16(sQ[0], qa, bh[0], bh[1]); mma16(sQ[0], qa, bl[0], bl[1]); mma16(sQ[0], ql, bh[0], bh[1]);
                    mma16(sQ[1], qa, bh[2], bh[3]); mma16(sQ[1], qa, bl[2], bl[3]); mma16(sQ[1], ql, bh[2], bh[3]);
                }
            }
        }
        // ---- A build (lower-triangle tiles only) ----
        if (sact) {
            int t0 = rt * 16 + gid, t1 = t0 + 8;
            float g0 = Gs[t0], g1 = Gs[t1];
            #pragma unroll
            for (int j = 0; j < 4; j++) {
                int s0 = ch * 32 + 8 * j + 2 * tig, s1 = s0 + 1;
                float gs0 = Gs[s0], gs1 = Gs[s1], w0 = WSs[s0], w1 = WSs[s1];
                float a00 = (t0 >= s0) ? ex2n(g0 - gs0) * w0 * sS[j][0] : 0.f;
                float a01 = (t0 >= s1) ? ex2n(g0 - gs1) * w1 * sS[j][1] : 0.f;
                float a10 = (t1 >= s0) ? ex2n(g1 - gs0) * w0 * sS[j][2] : 0.f;
                float a11 = (t1 >= s1) ? ex2n(g1 - gs1) * w1 * sS[j][3] : 0.f;
                uint32_t hi, lo;
                sp2(a00, a01, hi, lo);
                uint32_t o = (uint32_t)t0 * 144u + (uint32_t)(s0 << 1);
                *(uint32_t*)(sm + S_AH + o) = hi; *(uint32_t*)(sm + S_AL + o) = lo;
                sp2(a10, a11, hi, lo);
                o = (uint32_t)t1 * 144u + (uint32_t)(s0 << 1);
                *(uint32_t*)(sm + S_AH + o) = hi; *(uint32_t*)(sm + S_AL + o) = lo;
            }
        }
        // ---- V^T split store [32n x 64s] ----
        #pragma unroll
        for (int ii = 0; ii < 8; ii++) {
            int i = tid + ii * NT;
            int s = i >> 5, n = i & 31;
            __nv_bfloat16 h, l; spl(vreg[ii], h, l);
            uint32_t o = (uint32_t)n * 144u + (uint32_t)(s << 1);
            *(__nv_bfloat16*)(sm + S_VH + o) = h;
            *(__nv_bfloat16*)(sm + S_VL + o) = l;
        }
        __syncthreads();   // sync2

        // ---- GEMM2: AV (16x16, ks<=rt) and dM = K''^T V (16m x 32n) ----
        float sA[2][4], sD[4][4];
        #pragma unroll
        for (int j = 0; j < 2; j++)
            #pragma unroll
            for (int e = 0; e < 4; e++) sA[j][e] = 0.f;
        #pragma unroll
        for (int j = 0; j < 4; j++)
            #pragma unroll
            for (int e = 0; e < 4; e++) sD[j][e] = 0.f;
        {
            const uint32_t ahB = sb + S_AH + (uint32_t)(rt * 16) * 144u + laneA144;
            #pragma unroll
            for (int ks = 0; ks < 4; ks++) {
                if (ks <= rt) {
                    uint32_t aa[4], al[4];
                    ldmA(aa, ahB + ks * 32); ldmA(al, ahB + (S_AL - S_AH) + ks * 32);
                    uint32_t bh[4], bl[4];
                    uint32_t vB = sb + S_VH + (uint32_t)(ch * 16) * 144u + ks * 32 + laneB144x4;
                    ldmB4(bh, vB); ldmB4(bl, vB + (S_VL - S_VH));
                    mma16(sA[0], aa, bh[0], bh[1]); mma16(sA[0], aa, bl[0], bl[1]); mma16(sA[0], al, bh[0], bh[1]);
                    mma16(sA[1], aa, bh[2], bh[3]); mma16(sA[1], aa, bl[2], bl[3]); mma16(sA[1], al, bh[2], bh[3]);
                }
            }
            // dM: A-op = K^T (trans-ldmatrix) scaled by WG_s with exact re-split
            const uint32_t ktB = sb + S_KH + laneT + (uint32_t)(warp * 16) * 2u;
            #pragma unroll
            for (int ks = 0; ks < 4; ks++) {
                uint32_t kh4[4], kl4[4];
                ldmT(kh4, ktB + (uint32_t)(ks * 16) * 272u);
                ldmT(kl4, ktB + (S_KL - S_KH) + (uint32_t)(ks * 16) * 272u);
                int sA0 = ks * 16 + 2 * tig;
                float wg0 = WGs[sA0], wg1 = WGs[sA0 + 1];
                float wg2 = WGs[sA0 + 8], wg3 = WGs[sA0 + 9];
                uint32_t ka[4], kb[4];
                #pragma unroll
                for (int p = 0; p < 4; p++) {
                    float sw0 = (p < 2) ? wg0 : wg2;
                    float sw1 = (p < 2) ? wg1 : wg3;
                    __nv_bfloat162 H = *(__nv_bfloat162*)&kh4[p];
                    __nv_bfloat162 L = *(__nv_bfloat162*)&kl4[p];
                    float v0 = (__bfloat162float(H.x) + __bfloat162float(L.x)) * sw0;
                    float v1 = (__bfloat162float(H.y) + __bfloat162float(L.y)) * sw1;
                    sp2(v0, v1, ka[p], kb[p]);
                }
                #pragma unroll
                for (int jj = 0; jj < 2; jj++) {
                    uint32_t bh[4], bl[4];
                    uint32_t vB = sb + S_VH + (uint32_t)(jj * 16) * 144u + ks * 32 + laneB144x4;
                    ldmB4(bh, vB); ldmB4(bl, vB + (S_VL - S_VH));
                    mma16(sD[2*jj],   ka, bh[0], bh[1]); mma16(sD[2*jj],   ka, bl[0], bl[1]); mma16(sD[2*jj],   kb, bh[0], bh[1]);
                    mma16(sD[2*jj+1], ka, bh[2], bh[3]); mma16(sD[2*jj+1], ka, bl[2], bl[3]); mma16(sD[2*jj+1], kb, bh[2], bh[3]);
                }
            }
        }
        // ---- readout r = EG_t * QM0 + AV ----
        {
            int t0 = rt * 16 + gid, t1 = t0 + 8;
            float e0 = EGs[t0], e1 = EGs[t1];
            #pragma unroll
            for (int j = 0; j < 2; j++) {
                int n = vq * 32 + ch * 16 + 8 * j + 2 * tig;
                float2 o0 = make_float2(fmaf(e0, sQ[j][0], sA[j][0]), fmaf(e0, sQ[j][1], sA[j][1]));
                float2 o1 = make_float2(fmaf(e1, sQ[j][2], sA[j][2]), fmaf(e1, sQ[j][3], sA[j][3]));
                *(float2*)(out + (tb0 + t0) * 128 + n) = o0;
                *(float2*)(out + (tb0 + t1) * 128 + n) = o1;
            }
        }
        // ---- m0f = s63 * m0f + dM  (warp owns rows warp*16..+16, all 32 n) ----
        {
            float s63 = *(float*)(sm + S_SC);
            int mr0 = warp * 16 + gid, mr1 = mr0 + 8;
            #pragma unroll
            for (int j = 0; j < 4; j++) {
                int n = 8 * j + 2 * tig;
                float2* p0 = (float2*)(m0f + mr0 * 32 + n);
                float2* p1 = (float2*)(m0f + mr1 * 32 + n);
                float2 u0 = *p0, u1 = *p1;
                u0.x = fmaf(s63, u0.x, sD[j][0]); u0.y = fmaf(s63, u0.y, sD[j][1]);
                u1.x = fmaf(s63, u1.x, sD[j][2]); u1.y = fmaf(s63, u1.y, sD[j][3]);
                *p0 = u0; *p1 = u1;
            }
        }
        __syncthreads();   // sync3
    }
}

extern "C" void kernel_launch(void* const* d_in, const int* in_sizes, int n_in,
                              void* d_out, int out_size)
{
    (void)in_sizes; (void)n_in; (void)out_size;
    cudaFuncSetAttribute(lmm_hmma, cudaFuncAttributeMaxDynamicSharedMemorySize, SMEMB);
    lmm_hmma<<<256, NT, SMEMB>>>((const float*)d_in[0], (const float*)d_in[1],
                                 (const float*)d_in[2], (const float*)d_in[3],
                                 (const float*)d_in[4], (const float*)d_in[5],
                                 (const float*)d_in[6], (float*)d_out);
}

// round 13
// speedup vs baseline: 1.3678x; 1.3678x over previous
#include <cuda_runtime.h>
#include <cuda_bf16.h>
#include <cstdint>

#define TT 2048
#define CC 64
#define NCH 32
#define NT 512

// ---- smem (bytes). K tiles [64s x 128m] stride 272, double-buffered.
// MT [64n x 128m] stride 272. VT [64n x 64s] stride 144. A [64t x 64s] stride 144.
#define S_K0H 0
#define S_K0L 17408
#define S_K1H 34816
#define S_K1L 52224
#define S_MH  69632
#define S_ML  87040
#define S_VH  104448
#define S_VL  113664
#define S_AH  122880
#define S_AL  132096
#define S_G   141312
#define S_WS  141568
#define S_WG  141824
#define S_EG  142080
#define S_SC  142336
#define SMEMB 142592

static __device__ __forceinline__ uint32_t su32(const void* p) {
    uint32_t a;
    asm("{ .reg .u64 t; cvta.to.shared.u64 t, %1; cvt.u32.u64 %0, t; }" : "=r"(a) : "l"(p));
    return a;
}
static __device__ __forceinline__ void ldmA(uint32_t a[4], uint32_t addr) {
    asm volatile("ldmatrix.sync.aligned.m8n8.x4.shared.b16 {%0,%1,%2,%3}, [%4];"
        : "=r"(a[0]), "=r"(a[1]), "=r"(a[2]), "=r"(a[3]) : "r"(addr));
}
static __device__ __forceinline__ void ldmB4(uint32_t b[4], uint32_t addr) {
    asm volatile("ldmatrix.sync.aligned.m8n8.x4.shared.b16 {%0,%1,%2,%3}, [%4];"
        : "=r"(b[0]), "=r"(b[1]), "=r"(b[2]), "=r"(b[3]) : "r"(addr));
}
static __device__ __forceinline__ void ldmT(uint32_t a[4], uint32_t addr) {
    asm volatile("ldmatrix.sync.aligned.m8n8.x4.trans.shared.b16 {%0,%1,%2,%3}, [%4];"
        : "=r"(a[0]), "=r"(a[1]), "=r"(a[2]), "=r"(a[3]) : "r"(addr));
}
static __device__ __forceinline__ void mma16(float c[4], const uint32_t a[4], uint32_t b0, uint32_t b1) {
    asm volatile("mma.sync.aligned.m16n8k16.row.col.f32.bf16.bf16.f32 "
        "{%0,%1,%2,%3}, {%4,%5,%6,%7}, {%8,%9}, {%0,%1,%2,%3};"
        : "+f"(c[0]), "+f"(c[1]), "+f"(c[2]), "+f"(c[3])
        : "r"(a[0]), "r"(a[1]), "r"(a[2]), "r"(a[3]), "r"(b0), "r"(b1));
}
static __device__ __forceinline__ void spl(float x, __nv_bfloat16& h, __nv_bfloat16& l) {
    h = __float2bfloat16_rn(x);
    l = __float2bfloat16_rn(x - __bfloat162float(h));
}
static __device__ __forceinline__ void sp2(float x0, float x1, uint32_t& hi, uint32_t& lo) {
    __nv_bfloat16 h0, l0, h1, l1;
    spl(x0, h0, l0); spl(x1, h1, l1);
    hi = (uint32_t)__bfloat16_as_ushort(h0) | ((uint32_t)__bfloat16_as_ushort(h1) << 16);
    lo = (uint32_t)__bfloat16_as_ushort(l0) | ((uint32_t)__bfloat16_as_ushort(l1) << 16);
}
// exp2(x) for x <= 0, FFMA-only
static __device__ __forceinline__ float ex2n(float x) {
    float xc = fmaxf(x, -150.f);
    float xf = floorf(xc);
    float f  = xc - xf;
    float p = 1.54035e-4f;
    p = fmaf(p, f, 1.3335581e-3f);
    p = fmaf(p, f, 9.6181291e-3f);
    p = fmaf(p, f, 5.5504109e-2f);
    p = fmaf(p, f, 2.4022651e-1f);
    p = fmaf(p, f, 6.9314718e-1f);
    p = fmaf(p, f, 1.0f);
    float r = __int_as_float(__float_as_int(p) + (((int)xf) << 23));
    return (xc <= -126.f) ? 0.f : r;
}

__global__ void __launch_bounds__(NT, 1)
lmm_hmma(const float* __restrict__ q, const float* __restrict__ kk,
         const float* __restrict__ v, const float* __restrict__ alpha,
         const float* __restrict__ rho, const float* __restrict__ lam,
         const float* __restrict__ init, float* __restrict__ out)
{
    extern __shared__ char sm[];
    const uint32_t sb = su32(sm);
    const int tid = threadIdx.x, warp = tid >> 5, lane = tid & 31;
    const int gid = lane >> 2, tig = lane & 3;
    const int b = blockIdx.x >> 1, vh = blockIdx.x & 1;
    const int rt = warp >> 2, ct = warp & 3;   // S / QM0 / AV: 16x16 tile (rt, ct)
    const int wr = warp >> 1, wc = warp & 1;   // dM / M0: rows wr*16.., cols wc*32..
    float* Gs  = (float*)(sm + S_G);
    float* WSs = (float*)(sm + S_WS);
    float* WGs = (float*)(sm + S_WG);
    float* EGs = (float*)(sm + S_EG);

    const uint32_t laneA144 = (uint32_t)(lane & 15) * 144u + (uint32_t)((lane >> 4) << 4);
    const uint32_t laneB272x4 = (uint32_t)(lane & 7) * 272u + (uint32_t)(((lane >> 3) & 1) << 4)
                              + (uint32_t)(lane >> 4) * (8u * 272u);
    const uint32_t laneB144x4 = (uint32_t)(lane & 7) * 144u + (uint32_t)(((lane >> 3) & 1) << 4)
                              + (uint32_t)(lane >> 4) * (8u * 144u);
    const uint32_t laneT = ((uint32_t)(lane & 7) + (uint32_t)((lane >> 4) << 3)) * 272u
                         + (uint32_t)(lane & 8) * 2u;

    // ---- M0 permanently in registers: warp owns rows [wr*16, wr*16+16), cols [wc*32, +32) ----
    const int mr0 = wr * 16 + gid, mr1 = mr0 + 8;
    float m0[4][4];
    {
        const float* ip = init + (size_t)b * 16384 + vh * 64;
        #pragma unroll
        for (int j = 0; j < 4; j++) {
            int n = wc * 32 + 8 * j + 2 * tig;
            float2 f0 = *(const float2*)(ip + (size_t)mr0 * 128 + n);
            float2 f1 = *(const float2*)(ip + (size_t)mr1 * 128 + n);
            m0[j][0] = f0.x; m0[j][1] = f0.y; m0[j][2] = f1.x; m0[j][3] = f1.y;
        }
    }
    // write initial M^T tiles from regs
    #pragma unroll
    for (int j = 0; j < 4; j++) {
        int n = wc * 32 + 8 * j + 2 * tig;
        #pragma unroll
        for (int e = 0; e < 4; e++) {
            int nn = n + (e & 1), m = (e < 2) ? mr0 : mr1;
            __nv_bfloat16 h, l; spl(m0[j][e], h, l);
            uint32_t o = (uint32_t)nn * 272u + ((uint32_t)m << 1);
            *(__nv_bfloat16*)(sm + S_MH + o) = h;
            *(__nv_bfloat16*)(sm + S_ML + o) = l;
        }
    }
    // build K(0) tiles into buffer 0
    {
        const size_t t0 = (size_t)b * TT;
        for (int i = tid; i < 2048; i += NT) {
            int t = i >> 5, c4 = (i & 31) << 2;
            uint32_t o = (uint32_t)t * 272u + (uint32_t)(c4 << 1);
            float4 f = *(const float4*)(kk + (t0 + t) * 128 + c4);
            uint32_t h0, l0, h1, l1;
            sp2(f.x, f.y, h0, l0); sp2(f.z, f.w, h1, l1);
            *(uint32_t*)(sm + S_K0H + o) = h0; *(uint32_t*)(sm + S_K0H + o + 4) = h1;
            *(uint32_t*)(sm + S_K0L + o) = l0; *(uint32_t*)(sm + S_K0L + o + 4) = l1;
        }
    }
    // V(0) prefetch
    float vreg[8];
    #pragma unroll
    for (int ii = 0; ii < 8; ii++) {
        int i = tid + ii * NT;
        vreg[ii] = v[((size_t)b * TT + (size_t)(i >> 6)) * 128 + vh * 64 + (i & 63)];
    }

    for (int c = 0; c < NCH; c++) {
        const size_t tb0 = (size_t)b * TT + (size_t)c * CC;
        const uint32_t kbH = (c & 1) ? S_K1H : S_K0H;     // K(c) buffer
        const uint32_t nbH = (c & 1) ? S_K0H : S_K1H;     // K(c+1) buffer

        // ---- scalars (warp 0) ----
        if (warp == 0) {
            float x = log2f(fmaxf(lam[tb0 + lane], 1e-37f));
            #pragma unroll
            for (int o = 1; o < 32; o <<= 1) { float y = __shfl_up_sync(~0u, x, o); if (lane >= o) x += y; }
            float tot = __shfl_sync(~0u, x, 31);
            float y2 = log2f(fmaxf(lam[tb0 + 32 + lane], 1e-37f));
            #pragma unroll
            for (int o = 1; o < 32; o <<= 1) { float y = __shfl_up_sync(~0u, y2, o); if (lane >= o) y2 += y; }
            float g2 = tot + y2;
            float g63 = __shfl_sync(~0u, g2, 31);
            float w0 = rho[tb0 + lane] * alpha[tb0 + lane];
            float w1 = rho[tb0 + 32 + lane] * alpha[tb0 + 32 + lane];
            Gs[lane] = x;            Gs[32 + lane] = g2;
            WSs[lane] = w0;          WSs[32 + lane] = w1;
            EGs[lane] = ex2n(x);     EGs[32 + lane] = ex2n(g2);
            WGs[lane] = ex2n(g63 - x) * w0;
            WGs[32 + lane] = ex2n(g63 - g2) * w1;
            if (lane == 31) *(float*)(sm + S_SC) = ex2n(g63);
        }
        __syncthreads();   // sync1: scalars + M^T(c) + K(c) visible

        // ---- GEMM1: S = Qfrag K^T (ct<=rt) and QM0 = Qfrag M^T (K=128) ----
        const bool sact = (ct <= rt);
        float sS[2][4], sQ[2][4];
        #pragma unroll
        for (int j = 0; j < 2; j++)
            #pragma unroll
            for (int e = 0; e < 4; e++) { sS[j][e] = 0.f; sQ[j][e] = 0.f; }
        {
            const float* qr0 = q + (tb0 + (size_t)(rt * 16 + gid)) * 128 + 2 * tig;
            const uint32_t col = (uint32_t)(ct * 16);
            #pragma unroll
            for (int ks = 0; ks < 8; ks++) {
                uint32_t qa[4], ql[4];
                {
                    float2 f0 = *(const float2*)(qr0 + ks * 16);
                    float2 f1 = *(const float2*)(qr0 + 8 * 128 + ks * 16);
                    float2 f2 = *(const float2*)(qr0 + ks * 16 + 8);
                    float2 f3 = *(const float2*)(qr0 + 8 * 128 + ks * 16 + 8);
                    sp2(f0.x, f0.y, qa[0], ql[0]);
                    sp2(f1.x, f1.y, qa[1], ql[1]);
                    sp2(f2.x, f2.y, qa[2], ql[2]);
                    sp2(f3.x, f3.y, qa[3], ql[3]);
                }
                if (sact) {
                    uint32_t bh[4], bl[4];
                    uint32_t kB = sb + kbH + col * 272u + ks * 32 + laneB272x4;
                    ldmB4(bh, kB); ldmB4(bl, kB + 17408u);
                    mma16(sS[0], qa, bh[0], bh[1]); mma16(sS[0], qa, bl[0], bl[1]); mma16(sS[0], ql, bh[0], bh[1]);
                    mma16(sS[1], qa, bh[2], bh[3]); mma16(sS[1], qa, bl[2], bl[3]); mma16(sS[1], ql, bh[2], bh[3]);
                }
                {
                    uint32_t bh[4], bl[4];
                    uint32_t mB = sb + S_MH + col * 272u + ks * 32 + laneB272x4;
                    ldmB4(bh, mB); ldmB4(bl, mB + (S_ML - S_MH));
                    mma16(sQ[0], qa, bh[0], bh[1]); mma16(sQ[0], qa, bl[0], bl[1]); mma16(sQ[0], ql, bh[0], bh[1]);
                    mma16(sQ[1], qa, bh[2], bh[3]); mma16(sQ[1], qa, bl[2], bl[3]); mma16(sQ[1], ql, bh[2], bh[3]);
                }
            }
        }
        // ---- A build (lower triangle) ----
        if (sact) {
            int t0 = rt * 16 + gid, t1 = t0 + 8;
            float g0 = Gs[t0], g1 = Gs[t1];
            #pragma unroll
            for (int j = 0; j < 2; j++) {
                int s0 = ct * 16 + 8 * j + 2 * tig, s1 = s0 + 1;
                float gs0 = Gs[s0], gs1 = Gs[s1], w0 = WSs[s0], w1 = WSs[s1];
                float a00 = (t0 >= s0) ? ex2n(g0 - gs0) * w0 * sS[j][0] : 0.f;
                float a01 = (t0 >= s1) ? ex2n(g0 - gs1) * w1 * sS[j][1] : 0.f;
                float a10 = (t1 >= s0) ? ex2n(g1 - gs0) * w0 * sS[j][2] : 0.f;
                float a11 = (t1 >= s1) ? ex2n(g1 - gs1) * w1 * sS[j][3] : 0.f;
                uint32_t hi, lo;
                sp2(a00, a01, hi, lo);
                uint32_t o = (uint32_t)t0 * 144u + (uint32_t)(s0 << 1);
                *(uint32_t*)(sm + S_AH + o) = hi; *(uint32_t*)(sm + S_AL + o) = lo;
                sp2(a10, a11, hi, lo);
                o = (uint32_t)t1 * 144u + (uint32_t)(s0 << 1);
                *(uint32_t*)(sm + S_AH + o) = hi; *(uint32_t*)(sm + S_AL + o) = lo;
            }
        }
        // ---- V^T(c) store from regs [64n x 64s] ----
        #pragma unroll
        for (int ii = 0; ii < 8; ii++) {
            int i = tid + ii * NT;
            int s = i >> 6, n = i & 63;
            __nv_bfloat16 h, l; spl(vreg[ii], h, l);
            uint32_t o = (uint32_t)n * 144u + (uint32_t)(s << 1);
            *(__nv_bfloat16*)(sm + S_VH + o) = h;
            *(__nv_bfloat16*)(sm + S_VL + o) = l;
        }
        __syncthreads();   // sync2: A + V^T visible

        // ---- K(c+1) + V(c+1) prefetch to regs (DRAM latency hides under GEMM2) ----
        const size_t tb1 = tb0 + ((c + 1 < NCH) ? CC : 0);
        float4 kreg[4];
        #pragma unroll
        for (int ii = 0; ii < 4; ii++) {
            int i = tid + ii * NT;
            kreg[ii] = *(const float4*)(kk + (tb1 + (size_t)(i >> 5)) * 128 + ((i & 31) << 2));
        }
        #pragma unroll
        for (int ii = 0; ii < 8; ii++) {
            int i = tid + ii * NT;
            vreg[ii] = v[(tb1 + (size_t)(i >> 6)) * 128 + vh * 64 + (i & 63)];
        }

        // ---- GEMM2: AV (ks<=rt) ; dM mma directly into pre-scaled m0 regs ----
        float sA[2][4];
        #pragma unroll
        for (int j = 0; j < 2; j++)
            #pragma unroll
            for (int e = 0; e < 4; e++) sA[j][e] = 0.f;
        {
            const uint32_t ahB = sb + S_AH + (uint32_t)(rt * 16) * 144u + laneA144;
            #pragma unroll
            for (int ks = 0; ks < 4; ks++) {
                if (ks <= rt) {
                    uint32_t aa[4], al[4];
                    ldmA(aa, ahB + ks * 32); ldmA(al, ahB + (S_AL - S_AH) + ks * 32);
                    uint32_t bh[4], bl[4];
                    uint32_t vB = sb + S_VH + (uint32_t)(ct * 16) * 144u + ks * 32 + laneB144x4;
                    ldmB4(bh, vB); ldmB4(bl, vB + (S_VL - S_VH));
                    mma16(sA[0], aa, bh[0], bh[1]); mma16(sA[0], aa, bl[0], bl[1]); mma16(sA[0], al, bh[0], bh[1]);
                    mma16(sA[1], aa, bh[2], bh[3]); mma16(sA[1], aa, bl[2], bl[3]); mma16(sA[1], al, bh[2], bh[3]);
                }
            }
            // pre-scale m0 by s63, then accumulate dM into it
            float s63 = *(float*)(sm + S_SC);
            #pragma unroll
            for (int j = 0; j < 4; j++)
                #pragma unroll
                for (int e = 0; e < 4; e++) m0[j][e] *= s63;
            const uint32_t ktB = sb + kbH + laneT + ((uint32_t)(wr * 16) << 1);
            #pragma unroll
            for (int ks = 0; ks < 4; ks++) {
                uint32_t kh4[4], kl4[4];
                ldmT(kh4, ktB + (uint32_t)(ks * 16) * 272u);
                ldmT(kl4, ktB + 17408u + (uint32_t)(ks * 16) * 272u);
                int sA0 = ks * 16 + 2 * tig;
                float wg0 = WGs[sA0], wg1 = WGs[sA0 + 1];
                float wg2 = WGs[sA0 + 8], wg3 = WGs[sA0 + 9];
                uint32_t ka[4], kb2[4];
                #pragma unroll
                for (int p = 0; p < 4; p++) {
                    float sw0 = (p < 2) ? wg0 : wg2;
                    float sw1 = (p < 2) ? wg1 : wg3;
                    __nv_bfloat162 H = *(__nv_bfloat162*)&kh4[p];
                    __nv_bfloat162 L = *(__nv_bfloat162*)&kl4[p];
                    float v0 = (__bfloat162float(H.x) + __bfloat162float(L.x)) * sw0;
                    float v1 = (__bfloat162float(H.y) + __bfloat162float(L.y)) * sw1;
                    sp2(v0, v1, ka[p], kb2[p]);
                }
                #pragma unroll
                for (int jj = 0; jj < 2; jj++) {
                    uint32_t bh[4], bl[4];
                    uint32_t vB = sb + S_VH + (uint32_t)(wc * 32 + 16 * jj) * 144u + ks * 32 + laneB144x4;
                    ldmB4(bh, vB); ldmB4(bl, vB + (S_VL - S_VH));
                    mma16(m0[2*jj],   ka, bh[0], bh[1]); mma16(m0[2*jj],   ka, bl[0], bl[1]); mma16(m0[2*jj],   kb2, bh[0], bh[1]);
                    mma16(m0[2*jj+1], ka, bh[2], bh[3]); mma16(m0[2*jj+1], ka, bl[2], bl[3]); mma16(m0[2*jj+1], kb2, bh[2], bh[3]);
                }
            }
        }
        // ---- readout r = EG_t * QM0 + AV ----
        {
            int t0 = rt * 16 + gid, t1 = t0 + 8;
            float e0 = EGs[t0], e1 = EGs[t1];
            #pragma unroll
            for (int j = 0; j < 2; j++) {
                int n = ct * 16 + 8 * j + 2 * tig;
                float2 o0 = make_float2(fmaf(e0, sQ[j][0], sA[j][0]), fmaf(e0, sQ[j][1], sA[j][1]));
                float2 o1 = make_float2(fmaf(e1, sQ[j][2], sA[j][2]), fmaf(e1, sQ[j][3], sA[j][3]));
                *(float2*)(out + (tb0 + t0) * 128 + vh * 64 + n) = o0;
                *(float2*)(out + (tb0 + t1) * 128 + vh * 64 + n) = o1;
            }
        }
        // ---- STS K(c+1) into other buffer ----
        #pragma unroll
        for (int ii = 0; ii < 4; ii++) {
            int i = tid + ii * NT;
            int t = i >> 5, c4 = (i & 31) << 2;
            uint32_t o = (uint32_t)t * 272u + (uint32_t)(c4 << 1);
            uint32_t h0, l0, h1, l1;
            sp2(kreg[ii].x, kreg[ii].y, h0, l0); sp2(kreg[ii].z, kreg[ii].w, h1, l1);
            *(uint32_t*)(sm + nbH + o) = h0; *(uint32_t*)(sm + nbH + o + 4) = h1;
            *(uint32_t*)(sm + nbH + 17408u + o) = l0; *(uint32_t*)(sm + nbH + 17408u + o + 4) = l1;
        }
        // ---- write M^T(c+1) tiles from updated m0 regs ----
        #pragma unroll
        for (int j = 0; j < 4; j++) {
            int n = wc * 32 + 8 * j + 2 * tig;
            #pragma unroll
            for (int e = 0; e < 4; e++) {
                int nn = n + (e & 1), m = (e < 2) ? mr0 : mr1;
                __nv_bfloat16 h, l; spl(m0[j][e], h, l);
                uint32_t o = (uint32_t)nn * 272u + ((uint32_t)m << 1);
                *(__nv_bfloat16*)(sm + S_MH + o) = h;
                *(__nv_bfloat16*)(sm + S_ML + o) = l;
            }
        }
        __syncthreads();   // sync3
    }
}

extern "C" void kernel_launch(void* const* d_in, const int* in_sizes, int n_in,
                              void* d_out, int out_size)
{
    (void)in_sizes; (void)n_in; (void)out_size;
    cudaFuncSetAttribute(lmm_hmma, cudaFuncAttributeMaxDynamicSharedMemorySize, SMEMB);
    lmm_hmma<<<128, NT, SMEMB>>>((const float*)d_in[0], (const float*)d_in[1],
                                 (const float*)d_in[2], (const float*)d_in[3],
                                 (const float*)d_in[4], (const float*)d_in[5],
                                 (const float*)d_in[6], (float*)d_out);
}